// round 1
// baseline (speedup 1.0000x reference)
#include <cuda_runtime.h>
#include <cstdint>

// CCN promotion layer.
// tensors: [N, 3] f32 ; neigh: [N, 16] i32 (sorted per row)
// out = concat( promotions [N,16,16,16,3] f32 , new_parts [N,16] as f32 )
//
// promotions[n,c,a,b,s] = (nb[a]==nb[c] && nb[b]==nb[c]) ? tensors[nb[c]][s] : 0

static constexpr int D = 16;
static constexpr int F = 3;
static constexpr int PER_NODE = D * D * D * F;          // 12288 floats
static constexpr int PER_NODE_V4 = PER_NODE / 4;        // 3072 float4
static constexpr int THREADS = 256;
static constexpr int V4_PER_THREAD = PER_NODE_V4 / THREADS; // 12

__global__ __launch_bounds__(THREADS, 8)
void ccn_promo_kernel(const float* __restrict__ tensors,
                      const int*   __restrict__ neigh,
                      float*       __restrict__ out)
{
    const int n = blockIdx.x;
    const int t = threadIdx.x;

    __shared__ int      nb[D];
    __shared__ float    ft[D * F];
    __shared__ unsigned mask[D];

    if (t < D) nb[t] = neigh[n * D + t];
    __syncthreads();

    if (t < D * F) {
        int c = t / F;
        int s = t - c * F;
        ft[t] = tensors[nb[c] * F + s];
    }
    if (t < D) {
        const int my = nb[t];
        unsigned m = 0u;
        #pragma unroll
        for (int a = 0; a < D; a++)
            m |= (unsigned)(nb[a] == my) << a;
        mask[t] = m;
    }
    __syncthreads();

    float4* out4 = reinterpret_cast<float4*>(out + (size_t)n * PER_NODE);

    #pragma unroll
    for (int it = 0; it < V4_PER_THREAD; it++) {
        const int q = t + it * THREADS;        // float4 index within node
        const int base = q * 4;                // float index within node
        float e[4];
        #pragma unroll
        for (int k = 0; k < 4; k++) {
            const int idx = base + k;          // ((c*16+a)*16+b)*3+s
            const int ca  = idx / 48;          // c*16 + a
            const int bs  = idx - ca * 48;     // b*3 + s
            const int c   = ca >> 4;
            const int a   = ca & 15;
            const int b   = bs / 3;
            const int s   = bs - b * 3;
            const unsigned m = mask[c];
            const bool on = ((m >> a) & 1u) & ((m >> b) & 1u);
            e[k] = on ? ft[c * F + s] : 0.0f;
        }
        out4[q] = make_float4(e[0], e[1], e[2], e[3]);
    }
}

__global__ void ccn_parts_kernel(const int* __restrict__ neigh,
                                 float* __restrict__ out_parts,
                                 int count)
{
    int i = blockIdx.x * blockDim.x + threadIdx.x;
    if (i < count) out_parts[i] = (float)neigh[i];
}

extern "C" void kernel_launch(void* const* d_in, const int* in_sizes, int n_in,
                              void* d_out, int out_size)
{
    const float* tensors = (const float*)d_in[0];
    const int*   neigh   = (const int*)d_in[1];
    float*       out     = (float*)d_out;

    const int N = in_sizes[1] / D;           // neigh has N*D elements
    const long long promo_elems = (long long)N * PER_NODE;

    ccn_promo_kernel<<<N, THREADS>>>(tensors, neigh, out);

    const long long tail = (long long)out_size - promo_elems;
    if (tail == (long long)N * D) {
        int count = N * D;
        ccn_parts_kernel<<<(count + 255) / 256, 256>>>(
            neigh, out + promo_elems, count);
    }
}

// round 3
// speedup vs baseline: 1.7047x; 1.7047x over previous
#include <cuda_runtime.h>
#include <cstdint>

// CCN promotion layer, split into:
//  1) zero-fill of the whole promotions tensor (memset-rate stores)
//  2) sparse scatter of the ~48 nonzeros per node + new_parts tail
//
// tensors: [N, 3] f32 ; neigh: [N, 16] i32 (sorted per row)
// out = concat( promotions [N,16,16,16,3] f32 , new_parts [N,16] as f32 )
// promotions[n,c,a,b,s] = (nb[a]==nb[c] && nb[b]==nb[c]) ? tensors[nb[c]][s] : 0

static constexpr int D = 16;
static constexpr int F = 3;
static constexpr int PER_NODE = D * D * D * F;   // 12288 floats per node

// ---------------------------------------------------------------- zero fill
__global__ __launch_bounds__(256, 8)
void ccn_zero_kernel(float4* __restrict__ out4, long long count4)
{
    long long i      = (long long)blockIdx.x * blockDim.x + threadIdx.x;
    const long long stride = (long long)gridDim.x * blockDim.x;
    const float4 z = make_float4(0.f, 0.f, 0.f, 0.f);
    for (; i + 3 * stride < count4; i += 4 * stride) {
        out4[i]              = z;
        out4[i + stride]     = z;
        out4[i + 2 * stride] = z;
        out4[i + 3 * stride] = z;
    }
    for (; i < count4; i += stride) out4[i] = z;
}

// ---------------------------------------------------------------- scatter
// One warp per node. Lane c (< 16) owns row c of the chi mask.
__global__ __launch_bounds__(128, 16)
void ccn_scatter_kernel(const float* __restrict__ tensors,
                        const int*   __restrict__ neigh,
                        float*       __restrict__ out,
                        float*       __restrict__ out_parts,
                        int N)
{
    const int warp_global = (blockIdx.x * blockDim.x + threadIdx.x) >> 5;
    const int lane        = threadIdx.x & 31;
    if (warp_global >= N) return;
    const int n = warp_global;

    int my = 0;
    if (lane < D) my = neigh[n * D + lane];

    // equality mask via shfl (all 32 lanes participate in every shfl)
    unsigned m = 0u;
    #pragma unroll
    for (int a = 0; a < D; a++) {
        int va = __shfl_sync(0xFFFFFFFFu, my, a);
        m |= (unsigned)(va == my) << a;
    }

    if (lane >= D) return;

    // new_parts tail (neigh is pre-sorted; exact in fp32 since ids < 2^24)
    out_parts[n * D + lane] = (float)my;

    // feature of this lane's child
    const float f0 = tensors[my * F + 0];
    const float f1 = tensors[my * F + 1];
    const float f2 = tensors[my * F + 2];

    float* base = out + (size_t)n * PER_NODE + lane * (D * D * F); // row c = lane

    if (__popc(m) == 1) {
        // common case: only (a,b) = (c,c) is nonzero
        float* p = base + (lane * D + lane) * F;
        p[0] = f0; p[1] = f1; p[2] = f2;
    } else {
        unsigned ma = m;
        while (ma) {
            int a = __ffs(ma) - 1; ma &= ma - 1;
            unsigned mb = m;
            while (mb) {
                int b = __ffs(mb) - 1; mb &= mb - 1;
                float* p = base + (a * D + b) * F;
                p[0] = f0; p[1] = f1; p[2] = f2;
            }
        }
    }
}

// ---------------------------------------------------------------- launch
extern "C" void kernel_launch(void* const* d_in, const int* in_sizes, int n_in,
                              void* d_out, int out_size)
{
    const float* tensors = (const float*)d_in[0];
    const int*   neigh   = (const int*)d_in[1];
    float*       out     = (float*)d_out;

    const int N = in_sizes[1] / D;
    const long long promo_elems = (long long)N * PER_NODE;  // divisible by 4
    const long long count4 = promo_elems / 4;

    // 1) zero the promotions region at memset rate (2368 = 16 blocks x 148 SMs)
    ccn_zero_kernel<<<2368, 256>>>(reinterpret_cast<float4*>(out), count4);

    // 2) scatter nonzeros + write new_parts tail (only if tail present)
    const long long tail = (long long)out_size - promo_elems;
    float* out_parts = out + promo_elems;
    if (tail == (long long)N * D) {
        int threads = 128;
        int blocks = (N * 32 + threads - 1) / threads;
        ccn_scatter_kernel<<<blocks, threads>>>(tensors, neigh, out, out_parts, N);
    }
}

// round 4
// speedup vs baseline: 2.2702x; 1.3317x over previous
#include <cuda_runtime.h>
#include <cstdint>

// CCN promotion layer:
//  1) cudaMemsetAsync zero-fill of the promotions region (driver memset rate)
//  2) sparse scatter of the ~48 nonzeros per node + new_parts tail
//
// tensors: [N, 3] f32 ; neigh: [N, 16] i32 (sorted per row)
// out = concat( promotions [N,16,16,16,3] f32 , new_parts [N,16] as f32 )
// promotions[n,c,a,b,s] = (nb[a]==nb[c] && nb[b]==nb[c]) ? tensors[nb[c]][s] : 0

static constexpr int D = 16;
static constexpr int F = 3;
static constexpr int PER_NODE = D * D * D * F;   // 12288 floats per node

// ---------------------------------------------------------------- scatter
// TWO nodes per warp: lanes 0-15 -> node 2w, lanes 16-31 -> node 2w+1.
__global__ __launch_bounds__(256, 8)
void ccn_scatter_kernel(const float* __restrict__ tensors,
                        const int*   __restrict__ neigh,
                        float*       __restrict__ out,
                        float*       __restrict__ out_parts,
                        int N)
{
    const int warp_global = (blockIdx.x * blockDim.x + threadIdx.x) >> 5;
    const int lane        = threadIdx.x & 31;
    const int half        = lane >> 4;            // 0 or 1
    const int c           = lane & 15;            // slot within node
    const int n           = warp_global * 2 + half;
    const bool active     = (n < N);

    int my = 0;
    if (active) my = neigh[n * D + c];

    // equality mask within each 16-lane half-warp (all 32 lanes shfl)
    const int base_lane = half << 4;
    unsigned m = 0u;
    #pragma unroll
    for (int a = 0; a < D; a++) {
        int va = __shfl_sync(0xFFFFFFFFu, my, base_lane + a);
        m |= (unsigned)(va == my) << a;
    }

    if (!active) return;

    // new_parts tail (neigh is pre-sorted; exact in fp32 since ids < 2^24)
    out_parts[n * D + c] = (float)my;

    // feature of this lane's child
    const float f0 = tensors[my * F + 0];
    const float f1 = tensors[my * F + 1];
    const float f2 = tensors[my * F + 2];

    float* base = out + (size_t)n * PER_NODE + c * (D * D * F);   // row c

    if (__popc(m) == 1) {
        // common case: only (a,b) = (c,c) is nonzero
        float* p = base + (c * D + c) * F;
        p[0] = f0; p[1] = f1; p[2] = f2;
    } else {
        unsigned ma = m;
        while (ma) {
            int a = __ffs(ma) - 1; ma &= ma - 1;
            unsigned mb = m;
            while (mb) {
                int b = __ffs(mb) - 1; mb &= mb - 1;
                float* p = base + (a * D + b) * F;
                p[0] = f0; p[1] = f1; p[2] = f2;
            }
        }
    }
}

// ---------------------------------------------------------------- launch
extern "C" void kernel_launch(void* const* d_in, const int* in_sizes, int n_in,
                              void* d_out, int out_size)
{
    const float* tensors = (const float*)d_in[0];
    const int*   neigh   = (const int*)d_in[1];
    float*       out     = (float*)d_out;

    const int N = in_sizes[1] / D;
    const long long promo_elems = (long long)N * PER_NODE;

    // 1) zero the promotions region via driver memset (graph memset node)
    cudaMemsetAsync(out, 0, (size_t)promo_elems * sizeof(float), 0);

    // 2) scatter nonzeros + write new_parts tail (only if tail present)
    const long long tail = (long long)out_size - promo_elems;
    float* out_parts = out + promo_elems;
    if (tail == (long long)N * D) {
        // two nodes per warp -> N/2 warps
        int warps  = (N + 1) / 2;
        int threads = 256;
        int blocks  = (warps * 32 + threads - 1) / threads;
        ccn_scatter_kernel<<<blocks, threads>>>(tensors, neigh, out, out_parts, N);
    }
}

// round 5
// speedup vs baseline: 2.6671x; 1.1748x over previous
#include <cuda_runtime.h>
#include <cstdint>

// CCN promotion layer, fully fused: one block per node.
//   phase 1: zero the node's 48KB promotions region (12 x STG.128 per thread,
//            contiguous per-block layout -> memset-like page locality)
//   phase 2: warp 0 overwrites the ~48 nonzero floats (L2-merged, no DRAM RMW)
//
// tensors: [N, 3] f32 ; neigh: [N, 16] i32 (sorted per row)
// out = concat( promotions [N,16,16,16,3] f32 , new_parts [N,16] as f32 )
// promotions[n,c,a,b,s] = (nb[a]==nb[c] && nb[b]==nb[c]) ? tensors[nb[c]][s] : 0

static constexpr int D = 16;
static constexpr int F = 3;
static constexpr int PER_NODE    = D * D * D * F;      // 12288 floats
static constexpr int PER_NODE_V4 = PER_NODE / 4;       // 3072 float4
static constexpr int THREADS     = 256;
static constexpr int V4_PER_THR  = PER_NODE_V4 / THREADS;  // 12

__global__ __launch_bounds__(THREADS, 8)
void ccn_fused_kernel(const float* __restrict__ tensors,
                      const int*   __restrict__ neigh,
                      float*       __restrict__ out,
                      float*       __restrict__ out_parts,
                      int N, int write_parts)
{
    const int n = blockIdx.x;
    const int t = threadIdx.x;

    // ---- warp 0: start the gather chain early (loads overlap zero stores)
    int      my = 0;
    unsigned m  = 0u;
    float    f0 = 0.f, f1 = 0.f, f2 = 0.f;
    if (t < D) {
        my = neigh[n * D + t];
        // equality mask among lanes 0..15 in one instruction
        m = __match_any_sync(0x0000FFFFu, my) & 0xFFFFu;
        f0 = tensors[my * F + 0];
        f1 = tensors[my * F + 1];
        f2 = tensors[my * F + 2];
        if (write_parts)
            out_parts[n * D + t] = (float)my;   // exact: ids < 2^24
    }

    // ---- phase 1: zero this node's region, pure STG.128, no per-element ALU
    float4* out4 = reinterpret_cast<float4*>(out) + (size_t)n * PER_NODE_V4;
    const float4 z = make_float4(0.f, 0.f, 0.f, 0.f);
    #pragma unroll
    for (int k = 0; k < V4_PER_THR; k++)
        out4[t + k * THREADS] = z;

    __syncthreads();   // block-level fence: zeros visible before overwrites

    // ---- phase 2: overwrite nonzeros (hits just-zeroed L2 lines -> merged)
    if (t < D) {
        float* base = out + (size_t)n * PER_NODE + t * (D * D * F);  // row c = t

        if (__popc(m) == 1) {
            // common case: only (a,b) = (c,c)
            float* p = base + (t * D + t) * F;
            p[0] = f0; p[1] = f1; p[2] = f2;
        } else {
            unsigned ma = m;
            while (ma) {
                int a = __ffs(ma) - 1; ma &= ma - 1;
                unsigned mb = m;
                while (mb) {
                    int b = __ffs(mb) - 1; mb &= mb - 1;
                    float* p = base + (a * D + b) * F;
                    p[0] = f0; p[1] = f1; p[2] = f2;
                }
            }
        }
    }
}

extern "C" void kernel_launch(void* const* d_in, const int* in_sizes, int n_in,
                              void* d_out, int out_size)
{
    const float* tensors = (const float*)d_in[0];
    const int*   neigh   = (const int*)d_in[1];
    float*       out     = (float*)d_out;

    const int N = in_sizes[1] / D;
    const long long promo_elems = (long long)N * PER_NODE;
    const long long tail = (long long)out_size - promo_elems;
    const int write_parts = (tail == (long long)N * D) ? 1 : 0;
    float* out_parts = out + promo_elems;

    ccn_fused_kernel<<<N, THREADS>>>(tensors, neigh, out, out_parts,
                                     N, write_parts);
}